// round 2
// baseline (speedup 1.0000x reference)
#include <cuda_runtime.h>
#include <cuda_bf16.h>
#include <cstdint>

// RNN-T Transducer loss. Fixed shapes: B=32, T=256, U=128, V=4096, BLANK=0.
#define BB 32
#define TT 256
#define UU 128
#define VV 4096

#define BM 128
#define BN 64
#define BK 32
#define NKC (VV / BK)          // 128 k-chunks
#define A_TILE_ELEMS (BM * VV) // one (b,bt) tile of expE, tile-contiguous
#define B_TILE_ELEMS (BN * VV) // one (b,bu) tile of expP
#define A_STAGE_ELEMS (BM * BK) // 4096 elems = 8KB
#define B_STAGE_ELEMS (BN * BK) // 2048 elems = 4KB

// ---------------- scratch (device globals: no runtime allocation) ----------
// Tiled, pre-swizzled layouts:
//   g_expE: [tileA = b*2+bt (64)][kc (128)][chunk (512 = 128 rows x 4)][8 bf16]
//   g_expP: [tileB = b*2+bu (64)][kc (128)][chunk (256 =  64 rows x 4)][8 bf16]
__device__ __nv_bfloat16 g_expE[BB * TT * VV];   // 64 MB
__device__ __nv_bfloat16 g_expP[BB * UU * VV];   // 32 MB
__device__ float g_maxE[BB * TT];
__device__ float g_e0[BB * TT];
__device__ float g_maxP[BB * UU];
__device__ float g_p0[BB * UU];
__device__ float g_plab[BB * UU];
__device__ float g_blank[BB * TT * UU];          // 4 MB
__device__ float g_lab[BB * TT * UU];            // 4 MB (col U-1 unused)

// swizzled chunk index for (row, 16B-chunk c), 4 chunks per row of BK=32 bf16
__device__ __forceinline__ int schunk(int r, int c) { return r * 4 + (c ^ ((r >> 1) & 3)); }

// ---------------- pass 1: row max + exp + bf16 pack into tiled layout ------
// MODE 0: emissions  (B*T rows)  -> g_expE, g_maxE, g_e0
// MODE 1: predictions(B*U rows)  -> g_expP, g_maxP, g_p0, g_plab
template <int MODE>
__global__ void __launch_bounds__(256) prep_kernel(const float* __restrict__ src,
                                                   const int* __restrict__ labels)
{
    int row = blockIdx.x;
    const float* p = src + (size_t)row * VV;

    float4 v[4];
    float m = -INFINITY;
#pragma unroll
    for (int i = 0; i < 4; i++) {
        v[i] = *reinterpret_cast<const float4*>(p + i * 1024 + threadIdx.x * 4);
        m = fmaxf(m, fmaxf(fmaxf(v[i].x, v[i].y), fmaxf(v[i].z, v[i].w)));
    }
#pragma unroll
    for (int o = 16; o; o >>= 1) m = fmaxf(m, __shfl_xor_sync(0xffffffffu, m, o));

    __shared__ float sm[8];
    int lane = threadIdx.x & 31, wid = threadIdx.x >> 5;
    if (lane == 0) sm[wid] = m;
    __syncthreads();
    if (threadIdx.x < 8) {
        float t = sm[threadIdx.x];
#pragma unroll
        for (int o = 4; o; o >>= 1) t = fmaxf(t, __shfl_xor_sync(0xffu, t, o));
        if (threadIdx.x == 0) sm[0] = t;
    }
    __syncthreads();
    m = sm[0];

    // tiled destination
    size_t base; int r, kcElems;
    if (MODE == 0) {
        int b = row >> 8, t = row & 255;
        int tile = b * 2 + (t >> 7);
        r = t & 127;
        base = (size_t)tile * A_TILE_ELEMS;
        kcElems = A_STAGE_ELEMS;               // 4096 elems per kc block
    } else {
        int b = row >> 7, u = row & 127;
        int tile = b * 2 + (u >> 6);
        r = u & 63;
        base = (size_t)tile * B_TILE_ELEMS;
        kcElems = B_STAGE_ELEMS;               // 2048 elems per kc block
    }
    __nv_bfloat16* dst = (MODE == 0 ? g_expE : g_expP);

#pragma unroll
    for (int i = 0; i < 4; i++) {
        float ex = __expf(v[i].x - m), ey = __expf(v[i].y - m);
        float ez = __expf(v[i].z - m), ew = __expf(v[i].w - m);
        __nv_bfloat162 lo = __float22bfloat162_rn(make_float2(ex, ey));
        __nv_bfloat162 hi = __float22bfloat162_rn(make_float2(ez, ew));
        uint2 pk;
        pk.x = *reinterpret_cast<uint32_t*>(&lo);
        pk.y = *reinterpret_cast<uint32_t*>(&hi);
        int vi = i * 1024 + threadIdx.x * 4;
        int kc = vi >> 5;
        int c = (vi & 31) >> 3;
        int w = vi & 7;                        // 0 or 4
        size_t off = base + (size_t)kc * kcElems + (size_t)schunk(r, c) * 8 + w;
        *reinterpret_cast<uint2*>(dst + off) = pk;
    }

    if (threadIdx.x == 0) {
        if (MODE == 0) {
            g_maxE[row] = m;
            g_e0[row] = v[0].x;                // src[row, 0]
        } else {
            g_maxP[row] = m;
            g_p0[row] = v[0].x;
            int b = row / UU, u = row % UU;
            if (u < UU - 1) {
                int l = labels[b * (UU - 1) + u];
                g_plab[row] = p[l];
            }
        }
    }
}

// ---------------- bulk-copy + mbarrier helpers ------------------------------
__device__ __forceinline__ void bulk_ld(uint32_t sdst, const void* gsrc,
                                        uint32_t bytes, uint32_t bar)
{
    asm volatile(
        "cp.async.bulk.shared::cluster.global.mbarrier::complete_tx::bytes "
        "[%0], [%1], %2, [%3];\n"
        :: "r"(sdst), "l"(gsrc), "r"(bytes), "r"(bar) : "memory");
}

__device__ __forceinline__ void mbar_init(uint32_t bar, uint32_t cnt)
{
    asm volatile("mbarrier.init.shared.b64 [%0], %1;\n" :: "r"(bar), "r"(cnt) : "memory");
}

__device__ __forceinline__ void mbar_expect_tx(uint32_t bar, uint32_t bytes)
{
    asm volatile("mbarrier.arrive.expect_tx.shared.b64 _, [%0], %1;\n"
                 :: "r"(bar), "r"(bytes) : "memory");
}

__device__ __forceinline__ void mbar_wait(uint32_t bar, uint32_t parity)
{
    asm volatile(
        "{\n\t.reg .pred P;\n"
        "W_%=:\n\t"
        "mbarrier.try_wait.parity.acquire.cta.shared::cta.b64 P, [%0], %1;\n\t"
        "@!P bra W_%=;\n\t"
        "}\n"
        :: "r"(bar), "r"(parity) : "memory");
}

// ---------------- pass 2: bf16 tensor-core GEMM + fused epilogue ------------
// S[b,t,u] = sum_v expE[b,t,v] * expP[b,u,v]
// ln = log(S) + maxE + maxP ;  blank = e0+p0-ln ;  lab = e[t,lab[u]]+plab[u]-ln
__global__ void __launch_bounds__(256) gemm_kernel(const float* __restrict__ emissions,
                                                   const int* __restrict__ labels)
{
    __shared__ __nv_bfloat16 sA[3][A_STAGE_ELEMS];
    __shared__ __nv_bfloat16 sB[3][B_STAGE_ELEMS];
    __shared__ __align__(8) uint64_t mbar[3];

    int bt = blockIdx.x;      // T tile (0..1)
    int bu = blockIdx.y;      // U tile (0..1)
    int b  = blockIdx.z;
    int tid = threadIdx.x, lane = tid & 31, wid = tid >> 5;
    int warpM = wid >> 1, warpN = wid & 1;    // 4x2 warps, warp tile 32x32

    const __nv_bfloat16* gA = g_expE + (size_t)(b * 2 + bt) * A_TILE_ELEMS;
    const __nv_bfloat16* gB = g_expP + (size_t)(b * 2 + bu) * B_TILE_ELEMS;

    uint32_t barAddr[3], sAAddr[3], sBAddr[3];
#pragma unroll
    for (int s = 0; s < 3; s++) {
        barAddr[s] = (uint32_t)__cvta_generic_to_shared(&mbar[s]);
        sAAddr[s]  = (uint32_t)__cvta_generic_to_shared(&sA[s][0]);
        sBAddr[s]  = (uint32_t)__cvta_generic_to_shared(&sB[s][0]);
    }

    if (tid == 0) {
#pragma unroll
        for (int s = 0; s < 3; s++) mbar_init(barAddr[s], 1);
        asm volatile("fence.mbarrier_init.release.cluster;\n" ::: "memory");
    }
    __syncthreads();

    // producer issue for k-chunk k into stage k%3
    auto issueOK = 0; (void)issueOK;
    if (tid == 0) {
#pragma unroll
        for (int k = 0; k < 2; k++) {
            int s = k % 3;
            mbar_expect_tx(barAddr[s], (A_STAGE_ELEMS + B_STAGE_ELEMS) * 2);
            bulk_ld(sAAddr[s], gA + (size_t)k * A_STAGE_ELEMS, A_STAGE_ELEMS * 2, barAddr[s]);
            bulk_ld(sBAddr[s], gB + (size_t)k * B_STAGE_ELEMS, B_STAGE_ELEMS * 2, barAddr[s]);
        }
    }

    float acc[2][4][4];
#pragma unroll
    for (int i = 0; i < 2; i++)
#pragma unroll
        for (int j = 0; j < 4; j++)
#pragma unroll
            for (int e = 0; e < 4; e++) acc[i][j][e] = 0.0f;

    for (int k = 0; k < NKC; k++) {
        int buf = k % 3;
        __syncthreads();   // all warps done reading buffer (k-1)%3 == (k+2)%3
        if (tid == 0 && k + 2 < NKC) {
            int kn = k + 2, s = kn % 3;
            mbar_expect_tx(barAddr[s], (A_STAGE_ELEMS + B_STAGE_ELEMS) * 2);
            bulk_ld(sAAddr[s], gA + (size_t)kn * A_STAGE_ELEMS, A_STAGE_ELEMS * 2, barAddr[s]);
            bulk_ld(sBAddr[s], gB + (size_t)kn * B_STAGE_ELEMS, B_STAGE_ELEMS * 2, barAddr[s]);
        }
        mbar_wait(barAddr[buf], (k / 3) & 1);

#pragma unroll
        for (int ks = 0; ks < BK / 16; ks++) {
            int kk = ks * 16;
            uint32_t a[2][4];
#pragma unroll
            for (int mi = 0; mi < 2; mi++) {
                int r = warpM * 32 + mi * 16 + (lane & 15);
                int ch = (kk >> 3) + (lane >> 4);
                uint32_t addr = sAAddr[buf] + (uint32_t)schunk(r, ch) * 16;
                asm volatile("ldmatrix.sync.aligned.m8n8.x4.shared.b16 {%0,%1,%2,%3}, [%4];\n"
                             : "=r"(a[mi][0]), "=r"(a[mi][1]), "=r"(a[mi][2]), "=r"(a[mi][3])
                             : "r"(addr));
            }
            uint32_t bf[4][2];
#pragma unroll
            for (int jj = 0; jj < 2; jj++) {
                int r = warpN * 32 + jj * 16 + ((lane >> 4) * 8) + (lane & 7);
                int ch = (kk >> 3) + ((lane >> 3) & 1);
                uint32_t addr = sBAddr[buf] + (uint32_t)schunk(r, ch) * 16;
                uint32_t r0, r1, r2, r3;
                asm volatile("ldmatrix.sync.aligned.m8n8.x4.shared.b16 {%0,%1,%2,%3}, [%4];\n"
                             : "=r"(r0), "=r"(r1), "=r"(r2), "=r"(r3) : "r"(addr));
                bf[jj * 2][0] = r0; bf[jj * 2][1] = r1;
                bf[jj * 2 + 1][0] = r2; bf[jj * 2 + 1][1] = r3;
            }
#pragma unroll
            for (int mi = 0; mi < 2; mi++)
#pragma unroll
                for (int nj = 0; nj < 4; nj++) {
                    asm volatile(
                        "mma.sync.aligned.m16n8k16.row.col.f32.bf16.bf16.f32 "
                        "{%0,%1,%2,%3}, {%4,%5,%6,%7}, {%8,%9}, {%0,%1,%2,%3};\n"
                        : "+f"(acc[mi][nj][0]), "+f"(acc[mi][nj][1]),
                          "+f"(acc[mi][nj][2]), "+f"(acc[mi][nj][3])
                        : "r"(a[mi][0]), "r"(a[mi][1]), "r"(a[mi][2]), "r"(a[mi][3]),
                          "r"(bf[nj][0]), "r"(bf[nj][1]));
                }
        }
    }

    // fused epilogue
    int tbase = bt * BM + warpM * 32;
    int ubase = bu * BN + warpN * 32;
    int rA = lane >> 2, cB = 2 * (lane & 3);
#pragma unroll
    for (int mi = 0; mi < 2; mi++) {
#pragma unroll
        for (int nj = 0; nj < 4; nj++) {
#pragma unroll
            for (int e = 0; e < 4; e++) {
                int t = tbase + mi * 16 + rA + ((e >= 2) ? 8 : 0);
                int u = ubase + nj * 8 + cB + (e & 1);
                int rE = b * TT + t, rP = b * UU + u;
                float ln = __logf(acc[mi][nj][e]) + g_maxE[rE] + g_maxP[rP];
                int oidx = rE * UU + u;
                g_blank[oidx] = g_e0[rE] + g_p0[rP] - ln;
                if (u < UU - 1) {
                    int l = labels[b * (UU - 1) + u];
                    g_lab[oidx] = emissions[(size_t)rE * VV + l] + g_plab[rP] - ln;
                }
            }
        }
    }
}

// ---------------- pass 3: DP over (T,U) lattice -----------------------------
__device__ __forceinline__ float lse2(float x, float y)
{
    float m = fmaxf(x, y);
    if (m == -INFINITY) return m;
    return m + __logf(1.0f + __expf(-fabsf(x - y)));
}

__global__ void __launch_bounds__(UU) dp_kernel(const int* __restrict__ Tl_,
                                                const int* __restrict__ Ul_,
                                                float* __restrict__ out)
{
    int b = blockIdx.x;
    int u = threadIdx.x;
    int lane = u & 31, wid = u >> 5;
    int Tl = Tl_[b], Ul = Ul_[b];
    const float* blank = g_blank + (size_t)b * TT * UU;
    const float* lab   = g_lab   + (size_t)b * TT * UU;

    __shared__ float sp[4], sq[4];

    // row 0: alpha0[u] = sum_{i<u} lab[0,i]  (exclusive prefix sum)
    float s = (u >= 1) ? lab[u - 1] : 0.0f;
#pragma unroll
    for (int d = 1; d < 32; d <<= 1) {
        float t = __shfl_up_sync(0xffffffffu, s, d);
        if (lane >= d) s += t;
    }
    if (lane == 31) sp[wid] = s;
    __syncthreads();
    float pref = 0.0f;
    for (int w = 0; w < wid; w++) pref += sp[w];
    float alpha = s + pref;
    __syncthreads();

    if (Tl == 1 && u == Ul) out[b] = -(alpha + blank[Ul]);

    for (int t = 1; t < Tl; t++) {
        // recurrence x[u] = lse(q[u], x[u-1] + p[u]) via (P, Q) segment scan
        float p = (u >= 1) ? lab[t * UU + (u - 1)] : -INFINITY;
        float q = alpha + blank[(t - 1) * UU + u];
#pragma unroll
        for (int d = 1; d < 32; d <<= 1) {
            float pp = __shfl_up_sync(0xffffffffu, p, d);
            float qq = __shfl_up_sync(0xffffffffu, q, d);
            if (lane >= d) {
                q = lse2(q, qq + p);
                p = p + pp;
            }
        }
        if (lane == 31) { sp[wid] = p; sq[wid] = q; }
        __syncthreads();
        float Qw = -INFINITY;
        for (int w = 0; w < wid; w++) {
            float pw = sp[w], qw = sq[w];
            Qw = lse2(qw, Qw + pw);
        }
        if (wid > 0) q = lse2(q, Qw + p);
        alpha = q;
        __syncthreads();
        if (t == Tl - 1 && u == Ul) out[b] = -(alpha + blank[t * UU + Ul]);
    }
}

// ---------------- launch ----------------------------------------------------
extern "C" void kernel_launch(void* const* d_in, const int* in_sizes, int n_in,
                              void* d_out, int out_size)
{
    const float* emissions     = (const float*)d_in[0];
    const float* predictions   = (const float*)d_in[1];
    const int*   labels        = (const int*)d_in[2];
    const int*   input_lengths = (const int*)d_in[3];
    const int*   label_lengths = (const int*)d_in[4];
    float* out = (float*)d_out;

    prep_kernel<0><<<BB * TT, 256>>>(emissions, nullptr);
    prep_kernel<1><<<BB * UU, 256>>>(predictions, labels);
    gemm_kernel<<<dim3(TT / BM, UU / BN, BB), 256>>>(emissions, labels);
    dp_kernel<<<BB, UU>>>(input_lengths, label_lengths, out);
}

// round 8
// speedup vs baseline: 1.5531x; 1.5531x over previous
#include <cuda_runtime.h>
#include <cuda_bf16.h>
#include <cstdint>

// RNN-T Transducer loss. Fixed shapes: B=32, T=256, U=128, V=4096, BLANK=0.
#define BB 32
#define TT 256
#define UU 128
#define VV 4096
#define DDIM 384               // number of anti-diagonals (T+U-1=383), padded

#define BM 128
#define BN 64
#define BK 32
#define NKC (VV / BK)          // 128 k-chunks
#define A_TILE_ELEMS (BM * VV) // one (b,bt) tile of expE, tile-contiguous
#define B_TILE_ELEMS (BN * VV) // one (b,bu) tile of expP
#define A_STAGE_ELEMS (BM * BK) // 4096 elems = 8KB
#define B_STAGE_ELEMS (BN * BK) // 2048 elems = 4KB

// ---------------- scratch (device globals: no runtime allocation) ----------
// Tiled, pre-swizzled layouts:
//   g_expE: [tileA = b*2+bt (64)][kc (128)][chunk (512 = 128 rows x 4)][8 bf16]
//   g_expP: [tileB = b*2+bu (64)][kc (128)][chunk (256 =  64 rows x 4)][8 bf16]
__device__ __nv_bfloat16 g_expE[BB * TT * VV];   // 64 MB
__device__ __nv_bfloat16 g_expP[BB * UU * VV];   // 32 MB
__device__ float g_maxE[BB * TT];
__device__ float g_e0[BB * TT];
__device__ float g_maxP[BB * UU];
__device__ float g_p0[BB * UU];
__device__ float g_plab[BB * UU];
// diagonal-major lattice: g_bl[b][d = t+u][u] = (blank_lp[t,u], lab_lp[t,u])
__device__ float2 g_bl[BB * DDIM * UU];          // 12.6 MB

// swizzled chunk index for (row, 16B-chunk c), 4 chunks per row of BK=32 bf16
__device__ __forceinline__ int schunk(int r, int c) { return r * 4 + (c ^ ((r >> 1) & 3)); }

// ---------------- pass 1: row max + exp + bf16 pack into tiled layout ------
// Merged: blocks [0, BB*TT) handle emissions rows, the rest prediction rows.
__global__ void __launch_bounds__(256) prep_kernel(const float* __restrict__ emissions,
                                                   const float* __restrict__ predictions,
                                                   const int* __restrict__ labels)
{
    bool isE = blockIdx.x < BB * TT;
    int row = isE ? blockIdx.x : blockIdx.x - BB * TT;
    const float* p = (isE ? emissions : predictions) + (size_t)row * VV;

    float4 v[4];
    float m = -INFINITY;
#pragma unroll
    for (int i = 0; i < 4; i++) {
        v[i] = *reinterpret_cast<const float4*>(p + i * 1024 + threadIdx.x * 4);
        m = fmaxf(m, fmaxf(fmaxf(v[i].x, v[i].y), fmaxf(v[i].z, v[i].w)));
    }
#pragma unroll
    for (int o = 16; o; o >>= 1) m = fmaxf(m, __shfl_xor_sync(0xffffffffu, m, o));

    __shared__ float sm[8];
    int lane = threadIdx.x & 31, wid = threadIdx.x >> 5;
    if (lane == 0) sm[wid] = m;
    __syncthreads();
    if (threadIdx.x < 8) {
        float t = sm[threadIdx.x];
#pragma unroll
        for (int o = 4; o; o >>= 1) t = fmaxf(t, __shfl_xor_sync(0xffu, t, o));
        if (threadIdx.x == 0) sm[0] = t;
    }
    __syncthreads();
    m = sm[0];

    // tiled destination
    size_t base; int r, kcElems;
    if (isE) {
        int b = row >> 8, t = row & 255;
        int tile = b * 2 + (t >> 7);
        r = t & 127;
        base = (size_t)tile * A_TILE_ELEMS;
        kcElems = A_STAGE_ELEMS;               // 4096 elems per kc block
    } else {
        int b = row >> 7, u = row & 127;
        int tile = b * 2 + (u >> 6);
        r = u & 63;
        base = (size_t)tile * B_TILE_ELEMS;
        kcElems = B_STAGE_ELEMS;               // 2048 elems per kc block
    }
    __nv_bfloat16* dst = isE ? g_expE : g_expP;

#pragma unroll
    for (int i = 0; i < 4; i++) {
        float ex = __expf(v[i].x - m), ey = __expf(v[i].y - m);
        float ez = __expf(v[i].z - m), ew = __expf(v[i].w - m);
        __nv_bfloat162 lo = __float22bfloat162_rn(make_float2(ex, ey));
        __nv_bfloat162 hi = __float22bfloat162_rn(make_float2(ez, ew));
        uint2 pk;
        pk.x = *reinterpret_cast<uint32_t*>(&lo);
        pk.y = *reinterpret_cast<uint32_t*>(&hi);
        int vi = i * 1024 + threadIdx.x * 4;
        int kc = vi >> 5;
        int c = (vi & 31) >> 3;
        int w = vi & 7;                        // 0 or 4
        size_t off = base + (size_t)kc * kcElems + (size_t)schunk(r, c) * 8 + w;
        *reinterpret_cast<uint2*>(dst + off) = pk;
    }

    if (threadIdx.x == 0) {
        if (isE) {
            g_maxE[row] = m;
            g_e0[row] = v[0].x;                // src[row, 0]
        } else {
            g_maxP[row] = m;
            g_p0[row] = v[0].x;
            int b = row / UU, u = row % UU;
            if (u < UU - 1) {
                int l = labels[b * (UU - 1) + u];
                g_plab[row] = p[l];
            }
        }
    }
}

// ---------------- bulk-copy + mbarrier helpers ------------------------------
__device__ __forceinline__ void bulk_ld(uint32_t sdst, const void* gsrc,
                                        uint32_t bytes, uint32_t bar)
{
    asm volatile(
        "cp.async.bulk.shared::cluster.global.mbarrier::complete_tx::bytes "
        "[%0], [%1], %2, [%3];\n"
        :: "r"(sdst), "l"(gsrc), "r"(bytes), "r"(bar) : "memory");
}

__device__ __forceinline__ void mbar_init(uint32_t bar, uint32_t cnt)
{
    asm volatile("mbarrier.init.shared.b64 [%0], %1;\n" :: "r"(bar), "r"(cnt) : "memory");
}

__device__ __forceinline__ void mbar_expect_tx(uint32_t bar, uint32_t bytes)
{
    asm volatile("mbarrier.arrive.expect_tx.shared.b64 _, [%0], %1;\n"
                 :: "r"(bar), "r"(bytes) : "memory");
}

__device__ __forceinline__ void mbar_wait(uint32_t bar, uint32_t parity)
{
    asm volatile(
        "{\n\t.reg .pred P;\n"
        "W_%=:\n\t"
        "mbarrier.try_wait.parity.acquire.cta.shared::cta.b64 P, [%0], %1;\n\t"
        "@!P bra W_%=;\n\t"
        "}\n"
        :: "r"(bar), "r"(parity) : "memory");
}

// ---------------- pass 2: bf16 tensor-core GEMM + fused epilogue ------------
// S[b,t,u] = sum_v expE[b,t,v] * expP[b,u,v]
// ln = log(S) + maxE + maxP ;  blank = e0+p0-ln ;  lab = e[t,lab[u]]+plab[u]-ln
__global__ void __launch_bounds__(256) gemm_kernel(const float* __restrict__ emissions,
                                                   const int* __restrict__ labels)
{
    __shared__ __align__(1024) __nv_bfloat16 sA[3][A_STAGE_ELEMS];
    __shared__ __align__(1024) __nv_bfloat16 sB[3][B_STAGE_ELEMS];
    __shared__ __align__(8) uint64_t mbar[3];

    int bt = blockIdx.x;      // T tile (0..1)
    int bu = blockIdx.y;      // U tile (0..1)
    int b  = blockIdx.z;
    int tid = threadIdx.x, lane = tid & 31, wid = tid >> 5;
    int warpM = wid >> 1, warpN = wid & 1;    // 4x2 warps, warp tile 32x32

    const __nv_bfloat16* gA = g_expE + (size_t)(b * 2 + bt) * A_TILE_ELEMS;
    const __nv_bfloat16* gB = g_expP + (size_t)(b * 2 + bu) * B_TILE_ELEMS;

    uint32_t barAddr[3], sAAddr[3], sBAddr[3];
#pragma unroll
    for (int s = 0; s < 3; s++) {
        barAddr[s] = (uint32_t)__cvta_generic_to_shared(&mbar[s]);
        sAAddr[s]  = (uint32_t)__cvta_generic_to_shared(&sA[s][0]);
        sBAddr[s]  = (uint32_t)__cvta_generic_to_shared(&sB[s][0]);
    }

    if (tid == 0) {
#pragma unroll
        for (int s = 0; s < 3; s++) mbar_init(barAddr[s], 1);
        asm volatile("fence.mbarrier_init.release.cluster;\n" ::: "memory");
    }
    __syncthreads();

    if (tid == 0) {
#pragma unroll
        for (int k = 0; k < 2; k++) {
            int s = k % 3;
            mbar_expect_tx(barAddr[s], (A_STAGE_ELEMS + B_STAGE_ELEMS) * 2);
            bulk_ld(sAAddr[s], gA + (size_t)k * A_STAGE_ELEMS, A_STAGE_ELEMS * 2, barAddr[s]);
            bulk_ld(sBAddr[s], gB + (size_t)k * B_STAGE_ELEMS, B_STAGE_ELEMS * 2, barAddr[s]);
        }
    }

    float acc[2][4][4];
#pragma unroll
    for (int i = 0; i < 2; i++)
#pragma unroll
        for (int j = 0; j < 4; j++)
#pragma unroll
            for (int e = 0; e < 4; e++) acc[i][j][e] = 0.0f;

    for (int k = 0; k < NKC; k++) {
        int buf = k % 3;
        __syncthreads();   // all warps done reading buffer (k+2)%3 from prior lap
        if (tid == 0 && k + 2 < NKC) {
            int kn = k + 2, s = kn % 3;
            mbar_expect_tx(barAddr[s], (A_STAGE_ELEMS + B_STAGE_ELEMS) * 2);
            bulk_ld(sAAddr[s], gA + (size_t)kn * A_STAGE_ELEMS, A_STAGE_ELEMS * 2, barAddr[s]);
            bulk_ld(sBAddr[s], gB + (size_t)kn * B_STAGE_ELEMS, B_STAGE_ELEMS * 2, barAddr[s]);
        }
        mbar_wait(barAddr[buf], (k / 3) & 1);

#pragma unroll
        for (int ks = 0; ks < BK / 16; ks++) {
            int kk = ks * 16;
            uint32_t a[2][4];
#pragma unroll
            for (int mi = 0; mi < 2; mi++) {
                int r = warpM * 32 + mi * 16 + (lane & 15);
                int ch = (kk >> 3) + (lane >> 4);
                uint32_t addr = sAAddr[buf] + (uint32_t)schunk(r, ch) * 16;
                asm volatile("ldmatrix.sync.aligned.m8n8.x4.shared.b16 {%0,%1,%2,%3}, [%4];\n"
                             : "=r"(a[mi][0]), "=r"(a[mi][1]), "=r"(a[mi][2]), "=r"(a[mi][3])
                             : "r"(addr));
            }
            uint32_t bf[4][2];
#pragma unroll
            for (int jj = 0; jj < 2; jj++) {
                int r = warpN * 32 + jj * 16 + ((lane >> 4) * 8) + (lane & 7);
                int ch = (kk >> 3) + ((lane >> 3) & 1);
                uint32_t addr = sBAddr[buf] + (uint32_t)schunk(r, ch) * 16;
                uint32_t r0, r1, r2, r3;
                asm volatile("ldmatrix.sync.aligned.m8n8.x4.shared.b16 {%0,%1,%2,%3}, [%4];\n"
                             : "=r"(r0), "=r"(r1), "=r"(r2), "=r"(r3) : "r"(addr));
                bf[jj * 2][0] = r0; bf[jj * 2][1] = r1;
                bf[jj * 2 + 1][0] = r2; bf[jj * 2 + 1][1] = r3;
            }
#pragma unroll
            for (int mi = 0; mi < 2; mi++)
#pragma unroll
                for (int nj = 0; nj < 4; nj++) {
                    asm volatile(
                        "mma.sync.aligned.m16n8k16.row.col.f32.bf16.bf16.f32 "
                        "{%0,%1,%2,%3}, {%4,%5,%6,%7}, {%8,%9}, {%0,%1,%2,%3};\n"
                        : "+f"(acc[mi][nj][0]), "+f"(acc[mi][nj][1]),
                          "+f"(acc[mi][nj][2]), "+f"(acc[mi][nj][3])
                        : "r"(a[mi][0]), "r"(a[mi][1]), "r"(a[mi][2]), "r"(a[mi][3]),
                          "r"(bf[nj][0]), "r"(bf[nj][1]));
                }
        }
    }

    // fused epilogue: write diagonal-major float2 lattice
    int tbase = bt * BM + warpM * 32;
    int ubase = bu * BN + warpN * 32;
    int rA = lane >> 2, cB = 2 * (lane & 3);
#pragma unroll
    for (int mi = 0; mi < 2; mi++) {
#pragma unroll
        for (int nj = 0; nj < 4; nj++) {
#pragma unroll
            for (int e = 0; e < 4; e++) {
                int t = tbase + mi * 16 + rA + ((e >= 2) ? 8 : 0);
                int u = ubase + nj * 8 + cB + (e & 1);
                int rE = b * TT + t, rP = b * UU + u;
                float ln = __logf(acc[mi][nj][e]) + g_maxE[rE] + g_maxP[rP];
                float2 val;
                val.x = g_e0[rE] + g_p0[rP] - ln;          // blank log-prob
                val.y = 0.0f;
                if (u < UU - 1) {
                    int l = labels[b * (UU - 1) + u];
                    val.y = emissions[(size_t)rE * VV + l] + g_plab[rP] - ln;
                }
                g_bl[((size_t)b * DDIM + (t + u)) * UU + u] = val;
            }
        }
    }
}

// ---------------- pass 3: wavefront DP over anti-diagonals ------------------
__device__ __forceinline__ float lse2(float x, float y)
{
    float m = fmaxf(x, y);
    if (m == -INFINITY) return m;
    return m + __logf(1.0f + __expf(-fabsf(x - y)));
}

__global__ void __launch_bounds__(32) dp_kernel(const int* __restrict__ Tl_,
                                                const int* __restrict__ Ul_,
                                                float* __restrict__ out)
{
    const unsigned FULL = 0xffffffffu;
    int b = blockIdx.x;
    int lane = threadIdx.x;              // one warp per batch
    int Tl = Tl_[b], Ul = Ul_[b];
    int dstar = Tl - 1 + Ul;             // final diagonal index
    const float2* gbl = g_bl + (size_t)b * DDIM * UU;

    // alpha over diag 0: alpha[0,0] = 0, rest -inf. Thread holds u = lane+32k.
    float a[4];
#pragma unroll
    for (int k = 0; k < 4; k++) a[k] = -INFINITY;
    if (lane == 0) a[0] = 0.0f;

    // prefetch diag row 0
    float2 pf[4];
#pragma unroll
    for (int k = 0; k < 4; k++) pf[k] = __ldg(&gbl[lane + 32 * k]);

    for (int dd = 1; dd <= dstar; dd++) {
        float2 cur[4];
#pragma unroll
        for (int k = 0; k < 4; k++) cur[k] = pf[k];
        if (dd < dstar) {
#pragma unroll
            for (int k = 0; k < 4; k++)
                pf[k] = __ldg(&gbl[(size_t)dd * UU + lane + 32 * k]);
        }

        // neighbor (u-1) values from OLD alpha and current lab row
        float nb_a[4], nb_l[4];
#pragma unroll
        for (int k = 0; k < 4; k++) {
            float up_a = __shfl_up_sync(FULL, a[k], 1);
            float up_l = __shfl_up_sync(FULL, cur[k].y, 1);
            float wr_a = __shfl_sync(FULL, a[(k + 3) & 3], 31);
            float wr_l = __shfl_sync(FULL, cur[(k + 3) & 3].y, 31);
            nb_a[k] = lane ? up_a : (k ? wr_a : -INFINITY);
            nb_l[k] = lane ? up_l : wr_l;
        }
        // update: new[u] = lse(old[u] + blank[d-1][u], old[u-1] + lab[d-1][u-1])
#pragma unroll
        for (int k = 0; k < 4; k++) {
            float va = (a[k]    == -INFINITY) ? -INFINITY : a[k]    + cur[k].x;
            float vb = (nb_a[k] == -INFINITY) ? -INFINITY : nb_a[k] + nb_l[k];
            a[k] = lse2(va, vb);
        }
    }

    // cost = -(alpha[Tl-1, Ul] + blank[Tl-1, Ul]); cell (Tl-1, Ul) is on diag dstar
    if (lane == (Ul & 31)) {
        int k = Ul >> 5;
        float av = a[0];
        if (k == 1) av = a[1];
        else if (k == 2) av = a[2];
        else if (k == 3) av = a[3];
        float blankF = gbl[(size_t)dstar * UU + Ul].x;
        out[b] = -(av + blankF);
    }
}

// ---------------- launch ----------------------------------------------------
extern "C" void kernel_launch(void* const* d_in, const int* in_sizes, int n_in,
                              void* d_out, int out_size)
{
    const float* emissions     = (const float*)d_in[0];
    const float* predictions   = (const float*)d_in[1];
    const int*   labels        = (const int*)d_in[2];
    const int*   input_lengths = (const int*)d_in[3];
    const int*   label_lengths = (const int*)d_in[4];
    float* out = (float*)d_out;

    prep_kernel<<<BB * TT + BB * UU, 256>>>(emissions, predictions, labels);
    gemm_kernel<<<dim3(TT / BM, UU / BN, BB), 256>>>(emissions, labels);
    dp_kernel<<<BB, 32>>>(input_lengths, label_lengths, out);
}